// round 2
// baseline (speedup 1.0000x reference)
#include <cuda_runtime.h>
#include <math.h>

#define NBATCH 1024
#define NSEQ   200
#define NROWS  (NBATCH*NSEQ)   /* 204800 */

/* ------------ static scratch (no allocations allowed) ------------ */
__device__ float g_enc [NROWS*128];           /* encoder output                   */
__device__ float g_xpre[NROWS*1024];          /* precomputed gate preactivations  */
__device__ float g_hseq[NSEQ*NBATCH*256];     /* hx per step (output GEMM input)  */
__device__ float g_cx  [NBATCH*256];          /* cell state                       */
__device__ float g_predpart[2][16*NBATCH*2];  /* parity-buffered pred partials    */

typedef unsigned long long u64;

__device__ __forceinline__ u64 pack2(float lo, float hi){
    u64 r; asm("mov.b64 %0,{%1,%2};" : "=l"(r) : "f"(lo), "f"(hi)); return r;
}
__device__ __forceinline__ void unpack2(u64 v, float& lo, float& hi){
    asm("mov.b64 {%0,%1},%2;" : "=f"(lo), "=f"(hi) : "l"(v));
}
__device__ __forceinline__ u64 fma2(u64 a, u64 b, u64 c){
    u64 d; asm("fma.rn.f32x2 %0,%1,%2,%3;" : "=l"(d) : "l"(a), "l"(b), "l"(c)); return d;
}
__device__ __forceinline__ float sigmoidf_(float x){
    return __fdividef(1.0f, 1.0f + __expf(-x));
}

/* ================= Kernel 1: per-(b,t) set encoder ================= */
__global__ void enc_kernel(const float* __restrict__ coords,
                           const float* __restrict__ W_e1, const float* __restrict__ b_e1,
                           const float* __restrict__ W_e2, const float* __restrict__ b_e2)
{
    int rl = threadIdx.x >> 6;
    int j  = threadIdx.x & 63;
    size_t r = (size_t)blockIdx.x * 4 + rl;

    __shared__ float pt[4][44];
    __shared__ float m [4][2][64];

    if (j < 44) pt[rl][j] = coords[r*88 + ((j>>1)<<2) + (j&1)];
    __syncthreads();

    float w0 = W_e1[j], w1 = W_e1[64+j], bb = b_e1[j];
    float s1 = 0.f, s2 = 0.f;
#pragma unroll
    for (int p = 0; p < 11; p++){
        float hh = fmaf(pt[rl][2*p+1], w1, fmaf(pt[rl][2*p], w0, bb));
        s1 += fmaxf(hh, 0.f);
    }
#pragma unroll
    for (int p = 11; p < 22; p++){
        float hh = fmaf(pt[rl][2*p+1], w1, fmaf(pt[rl][2*p], w0, bb));
        s2 += fmaxf(hh, 0.f);
    }
    m[rl][0][j] = s1 * (1.0f/11.0f);
    m[rl][1][j] = s2 * (1.0f/11.0f);
    __syncthreads();

    float o1 = b_e2[j], o2 = b_e2[j];
#pragma unroll
    for (int k = 0; k < 64; k++){
        float w = W_e2[k*64 + j];
        o1 = fmaf(m[rl][0][k], w, o1);
        o2 = fmaf(m[rl][1][k], w, o2);
    }
    g_enc[r*128 + j]      = o1;
    g_enc[r*128 + 64 + j] = o2;
}

/* ================= Kernel 2: Xpre GEMM =================
   g_xpre[r][h*64 + c] where c = gate*16 + u maps to W_ih col gate*256+h*16+u. */
__global__ void __launch_bounds__(256) xpre_kernel(
    const float* __restrict__ coords, const float* __restrict__ W_ih,
    const float* __restrict__ b_ih,   const float* __restrict__ b_hh)
{
    extern __shared__ float smx[];
    float* a_s = smx;            /* 32*132 = 4224 */
    float* w_s = a_s + 4224;     /* 32*64  = 2048 */
    float* epi = w_s + 2048;     /* 128*65 = 8320 */

    int h  = blockIdx.x;
    size_t m0 = (size_t)blockIdx.y * 128;
    int tid = threadIdx.x;
    int tb = tid & 31, tu = tid >> 5;

    u64 acc2[4][4];
#pragma unroll
    for (int bi=0;bi<4;bi++)
#pragma unroll
        for (int g=0;g<4;g++) acc2[bi][g] = 0ULL;

    for (int k0 = 0; k0 < 172; k0 += 32){
#pragma unroll
        for (int i = 0; i < 16; i++){
            int li  = tid + i*256;
            int kk  = li & 31, row = li >> 5;
            int k   = k0 + kk;
            float v = 0.f;
            size_t r = m0 + row;
            if (k < 44)       v = coords[r*88 + ((k>>1)<<2) + (k&1)];
            else if (k < 172) v = g_enc[r*128 + (k-44)];
            a_s[kk*132 + row] = v;
        }
#pragma unroll
        for (int i = 0; i < 8; i++){
            int li = tid + i*256;
            int c  = li & 63, kk = li >> 6;
            int k  = k0 + kk;
            float v = 0.f;
            if (k < 172){
                int col = ((c>>4)<<8) + (h<<4) + (c&15);
                v = W_ih[k*1024 + col];
            }
            w_s[kk*64 + c] = v;
        }
        __syncthreads();
#pragma unroll
        for (int kk = 0; kk < 32; kk++){
            float4 a = *(const float4*)&a_s[kk*132 + 4*tb];
            u64 ax = pack2(a.x,a.x), ay = pack2(a.y,a.y);
            u64 az = pack2(a.z,a.z), aw = pack2(a.w,a.w);
            int kw = kk*64 + (tu<<1);
#pragma unroll
            for (int g = 0; g < 4; g++){
                u64 w2 = *(const u64*)&w_s[kw + g*16];
                acc2[0][g] = fma2(ax, w2, acc2[0][g]);
                acc2[1][g] = fma2(ay, w2, acc2[1][g]);
                acc2[2][g] = fma2(az, w2, acc2[2][g]);
                acc2[3][g] = fma2(aw, w2, acc2[3][g]);
            }
        }
        __syncthreads();
    }

    /* epilogue: biases + staged coalesced store */
#pragma unroll
    for (int g = 0; g < 4; g++){
        int col0 = (g<<8) + (h<<4) + 2*tu;
        float b0 = b_ih[col0]   + b_hh[col0];
        float b1 = b_ih[col0+1] + b_hh[col0+1];
#pragma unroll
        for (int bi = 0; bi < 4; bi++){
            float lo, hi; unpack2(acc2[bi][g], lo, hi);
            epi[(4*tb+bi)*65 + g*16 + 2*tu]     = lo + b0;
            epi[(4*tb+bi)*65 + g*16 + 2*tu + 1] = hi + b1;
        }
    }
    __syncthreads();
#pragma unroll
    for (int i = 0; i < 8; i++){
        int li = tid + i*256;
        int row = li >> 4, c4 = li & 15;
        size_t r = m0 + row;
        float4 v = make_float4(epi[row*65 + 4*c4],   epi[row*65 + 4*c4+1],
                               epi[row*65 + 4*c4+2], epi[row*65 + 4*c4+3]);
        *(float4*)&g_xpre[r*1024 + (size_t)h*64 + 4*c4] = v;
    }
}

/* ================= Kernel 3: one recurrent step =================
   grid (16, 8): h = hid-tile, bm = batch-tile (128 rows each).
   Kernel boundary = global barrier; no software sync.               */
__global__ void __launch_bounds__(256) rnn_step_kernel(
    const float* __restrict__ coords, const float* __restrict__ W_ih,
    const float* __restrict__ W_hh,   const float* __restrict__ W_out,
    const float* __restrict__ b_out,  const float* __restrict__ pitch, int t)
{
    extern __shared__ float sm[];
    float* w_s    = sm;                    /* 16384: W_hh slice [256][64] */
    float* hx_s   = w_s    + 16384;        /* 32*132 */
    float* xpre_s = hx_s   + 4224;         /* 128*64 */
    float* epi    = xpre_s + 8192;         /* 128*17 */
    float* clo_s  = epi    + 2176;         /* 128 */
    float* px_s   = clo_s  + 128;
    float* py_s   = px_s   + 128;
    float* wo_s   = py_s   + 128;          /* 32 */

    int h = blockIdx.x, bm = blockIdx.y;
    int tid = threadIdx.x, tb = tid & 31, tu = tid >> 5;

    /* W_hh slice -> smem (permuted cols, float4) */
#pragma unroll
    for (int i = 0; i < 16; i++){
        int li = tid + i*256;              /* 4096 f4 = 256 k x 16 c4 */
        int c4 = li & 15, k = li >> 4;
        int col = ((c4>>2)<<8) + (h<<4) + ((c4&3)<<2);
        *(float4*)&w_s[k*64 + c4*4] = *(const float4*)&W_hh[k*1024 + col];
    }
    if (tid < 32){
        int u = tid >> 1, d = tid & 1;
        wo_s[tid] = W_out[(h*16+u)*90 + 88 + d];
    }

    /* critical-path W_ih rows (closest, pred_x, pred_y) */
    float cw[4][2], pxw[4][2], pyw[4][2];
#pragma unroll
    for (int g = 0; g < 4; g++)
#pragma unroll
        for (int ui = 0; ui < 2; ui++){
            int col = (g<<8) + (h<<4) + 2*tu + ui;
            cw [g][ui] = W_ih[172*1024 + col];
            pxw[g][ui] = W_ih[173*1024 + col];
            pyw[g][ui] = W_ih[174*1024 + col];
        }
    float ps0 = pitch[0], ps1 = pitch[1];
    float bo88 = b_out[88], bo89 = b_out[89];

    /* pred (sum of parity-buffered partials) + closest distance */
    if (tid < 128){
        size_t bg = (size_t)bm*128 + tid;
        float px = 0.f, py = 0.f;
        if (t > 0){
            const float* pp = g_predpart[(t-1)&1];
#pragma unroll
            for (int hh = 0; hh < 16; hh++){
                float2 v = *(const float2*)&pp[((size_t)hh*1024 + bg)*2];
                px += v.x; py += v.y;
            }
            px = (px + bo88) * ps0;
            py = (py + bo89) * ps1;
        }
        const float* cp = coords + (bg*NSEQ + t)*88;
        float md = 3.402823e38f;
#pragma unroll
        for (int p = 0; p < 22; p++){
            float dx = px - cp[4*p], dy = py - cp[4*p+1];
            md = fminf(md, fmaf(dx,dx,dy*dy));
        }
        clo_s[tid] = sqrtf(md);
        px_s[tid] = px; py_s[tid] = py;
    }

    /* Xpre tile -> smem */
#pragma unroll
    for (int i = 0; i < 8; i++){
        int li = tid + i*256;
        int row = li >> 4, c4 = li & 15;
        size_t r = ((size_t)(bm*128 + row))*NSEQ + t;
        *(float4*)&xpre_s[row*64 + 4*c4] =
            *(const float4*)&g_xpre[r*1024 + (size_t)h*64 + 4*c4];
    }

    u64 acc2[4][4];
#pragma unroll
    for (int bi=0;bi<4;bi++)
#pragma unroll
        for (int g=0;g<4;g++) acc2[bi][g] = 0ULL;

    if (t > 0){
        const float* hx = g_hseq + ((size_t)(t-1)*1024 + bm*128)*256;
        for (int kc = 0; kc < 8; kc++){
            __syncthreads();
#pragma unroll
            for (int i = 0; i < 4; i++){
                int li = tid + i*256;      /* 1024 f4 = 128 rows x 8 f4 */
                int row = li >> 3, c4 = li & 7;
                float4 v = *(const float4*)&hx[row*256 + kc*32 + 4*c4];
                hx_s[(4*c4+0)*132 + row] = v.x;
                hx_s[(4*c4+1)*132 + row] = v.y;
                hx_s[(4*c4+2)*132 + row] = v.z;
                hx_s[(4*c4+3)*132 + row] = v.w;
            }
            __syncthreads();
#pragma unroll
            for (int kk = 0; kk < 32; kk++){
                float4 a = *(const float4*)&hx_s[kk*132 + 4*tb];
                u64 ax = pack2(a.x,a.x), ay = pack2(a.y,a.y);
                u64 az = pack2(a.z,a.z), aw = pack2(a.w,a.w);
                int kw = (kc*32 + kk)*64 + (tu<<1);
#pragma unroll
                for (int g = 0; g < 4; g++){
                    u64 w2 = *(const u64*)&w_s[kw + g*16];
                    acc2[0][g] = fma2(ax, w2, acc2[0][g]);
                    acc2[1][g] = fma2(ay, w2, acc2[1][g]);
                    acc2[2][g] = fma2(az, w2, acc2[2][g]);
                    acc2[3][g] = fma2(aw, w2, acc2[3][g]);
                }
            }
        }
    }
    __syncthreads();

    /* LSTM elementwise; cx streamed through global */
#pragma unroll
    for (int bi = 0; bi < 4; bi++){
        int row = 4*tb + bi;
        float clo = clo_s[row], ppx = px_s[row], ppy = py_s[row];
        size_t cxa = ((size_t)(bm*128 + row))*256 + h*16 + 2*tu;
        float2 cxv = (t > 0) ? *(const float2*)&g_cx[cxa] : make_float2(0.f, 0.f);

        float gl[4][2];
#pragma unroll
        for (int g = 0; g < 4; g++){
            float lo, hi; unpack2(acc2[bi][g], lo, hi);
            int u0 = 2*tu;
            gl[g][0] = lo + xpre_s[row*64 + g*16 + u0]
                          + clo*cw[g][0] + ppx*pxw[g][0] + ppy*pyw[g][0];
            gl[g][1] = hi + xpre_s[row*64 + g*16 + u0 + 1]
                          + clo*cw[g][1] + ppx*pxw[g][1] + ppy*pyw[g][1];
        }
        float c20 = sigmoidf_(gl[1][0])*cxv.x + sigmoidf_(gl[0][0])*tanhf(gl[2][0]);
        float c21 = sigmoidf_(gl[1][1])*cxv.y + sigmoidf_(gl[0][1])*tanhf(gl[2][1]);
        float h20 = sigmoidf_(gl[3][0])*tanhf(c20);
        float h21 = sigmoidf_(gl[3][1])*tanhf(c21);
        *(float2*)&g_cx[cxa] = make_float2(c20, c21);
        epi[row*17 + 2*tu]     = h20;
        epi[row*17 + 2*tu + 1] = h21;
    }
    __syncthreads();

    /* coalesced hseq store */
    {
        float* hout = g_hseq + ((size_t)t*1024 + bm*128)*256 + h*16;
#pragma unroll
        for (int i = 0; i < 8; i++){
            int li = tid + i*256;          /* 2048 = 128 x 16 */
            int row = li >> 4, c = li & 15;
            hout[row*256 + c] = epi[row*17 + c];
        }
    }
    /* deterministic pred partials for step t+1 */
    if (tid < 128){
        size_t bg = (size_t)bm*128 + tid;
        float px = 0.f, py = 0.f;
#pragma unroll
        for (int u = 0; u < 16; u++){
            float hv = epi[tid*17 + u];
            px = fmaf(hv, wo_s[2*u],   px);
            py = fmaf(hv, wo_s[2*u+1], py);
        }
        *(float2*)&g_predpart[t&1][((size_t)h*1024 + bg)*2] = make_float2(px, py);
    }
}

/* ================= Kernel 4: output head GEMM ================= */
__global__ void __launch_bounds__(256) out_kernel(
    const float* __restrict__ W_out, const float* __restrict__ b_out,
    const float* __restrict__ pitch, float* __restrict__ out)
{
    size_t r0 = (size_t)blockIdx.x * 64;
    int tid = threadIdx.x;
    int tx = tid & 15, ty = tid >> 4;

    __shared__ float a_s[32*68];
    __shared__ float w_s[32*96];

    float acc[4][6];
#pragma unroll
    for (int bi=0;bi<4;bi++)
#pragma unroll
        for (int ci=0;ci<6;ci++) acc[bi][ci]=0.f;

    for (int k0 = 0; k0 < 256; k0 += 32){
#pragma unroll
        for (int i = 0; i < 8; i++){
            int li = tid + i*256;
            int kk = li & 31, row = li >> 5;
            size_t r = r0 + row;
            int t = (int)(r % NSEQ), b = (int)(r / NSEQ);
            a_s[kk*68 + row] = g_hseq[((size_t)t*1024 + b)*256 + k0 + kk];
        }
#pragma unroll
        for (int i = 0; i < 12; i++){
            int li = tid + i*256;
            int n = li % 96, kk = li / 96;
            w_s[kk*96 + n] = (n < 90) ? W_out[(k0+kk)*90 + n] : 0.f;
        }
        __syncthreads();
#pragma unroll
        for (int kk = 0; kk < 32; kk++){
            float4 a = *(const float4*)&a_s[kk*68 + 4*ty];
            float w[6];
#pragma unroll
            for (int ci = 0; ci < 6; ci++) w[ci] = w_s[kk*96 + 6*tx + ci];
#pragma unroll
            for (int ci = 0; ci < 6; ci++){
                acc[0][ci] = fmaf(a.x, w[ci], acc[0][ci]);
                acc[1][ci] = fmaf(a.y, w[ci], acc[1][ci]);
                acc[2][ci] = fmaf(a.z, w[ci], acc[2][ci]);
                acc[3][ci] = fmaf(a.w, w[ci], acc[3][ci]);
            }
        }
        __syncthreads();
    }
#pragma unroll
    for (int bi = 0; bi < 4; bi++){
        size_t r = r0 + 4*ty + bi;
#pragma unroll
        for (int ci = 0; ci < 6; ci++){
            int n = 6*tx + ci;
            if (n < 90)
                out[r*90 + n] = (acc[bi][ci] + b_out[n]) * pitch[n & 1];
        }
    }
}

/* ================= host launcher ================= */
extern "C" void kernel_launch(void* const* d_in, const int* in_sizes, int n_in,
                              void* d_out, int out_size)
{
    const float* coords = (const float*)d_in[0];
    const float* pitch  = (const float*)d_in[1];
    const float* W_e1   = (const float*)d_in[2];
    const float* b_e1   = (const float*)d_in[3];
    const float* W_e2   = (const float*)d_in[4];
    const float* b_e2   = (const float*)d_in[5];
    const float* W_ih   = (const float*)d_in[6];
    const float* b_ih   = (const float*)d_in[7];
    const float* W_hh   = (const float*)d_in[8];
    const float* b_hh   = (const float*)d_in[9];
    const float* W_out  = (const float*)d_in[10];
    const float* b_out  = (const float*)d_in[11];
    float* out = (float*)d_out;

    static int attr_done = 0;
    size_t xpre_smem = 14592u * sizeof(float);   /* 58,368 B  */
    size_t rnn_smem  = 31392u * sizeof(float);   /* 125,568 B */
    if (!attr_done){
        cudaFuncSetAttribute(xpre_kernel, cudaFuncAttributeMaxDynamicSharedMemorySize,
                             (int)xpre_smem);
        cudaFuncSetAttribute(rnn_step_kernel, cudaFuncAttributeMaxDynamicSharedMemorySize,
                             (int)rnn_smem);
        attr_done = 1;
    }

    enc_kernel<<<NROWS/4, 256>>>(coords, W_e1, b_e1, W_e2, b_e2);
    xpre_kernel<<<dim3(16, NROWS/128), 256, xpre_smem>>>(coords, W_ih, b_ih, b_hh);

    for (int t = 0; t < NSEQ; t++)
        rnn_step_kernel<<<dim3(16, 8), 256, rnn_smem>>>(
            coords, W_ih, W_hh, W_out, b_out, pitch, t);

    out_kernel<<<NROWS/64, 256>>>(W_out, b_out, pitch, out);
}